// round 7
// baseline (speedup 1.0000x reference)
#include <cuda_runtime.h>
#include <math.h>

#define BB 1024
#define TT 200
#define EE 64
#define UU 64
#define HH 4
#define DH 16
#define C3U 192

typedef unsigned long long ull;
typedef unsigned int u32;
typedef unsigned short u16;

// Scratch (allocation-free rule)
__device__ float g_qkv[(size_t)BB * TT * C3U];    // [B,T,3U] row-major
__device__ float g_attn[(size_t)BB * TT * UU];    // [B,T,U]  row-major
// W^T split into bf16 hi/lo, padded rows of 72 bf16 (144B): [hi: 192x72][lo: 192x72]
__device__ __align__(16) u16 g_wq[2 * 192 * 72];
// Wo^T split: [hi: 64x72][lo: 64x72]
__device__ __align__(16) u16 g_wo[2 * 64 * 72];

// ---------------------------------------------------------------------------
__device__ __forceinline__ u16 f2bf(float f) {           // round-to-nearest-even
    u32 u = __float_as_uint(f);
    u32 r = u + 0x7FFFu + ((u >> 16) & 1u);
    return (u16)(r >> 16);
}
__device__ __forceinline__ float bf2f(u16 b) {
    return __uint_as_float(((u32)b) << 16);
}

__device__ __forceinline__ ull pack2(float x, float y) {
    ull r; asm("mov.b64 %0, {%1, %2};" : "=l"(r) : "f"(x), "f"(y)); return r;
}
__device__ __forceinline__ void unpack2(ull v, float& x, float& y) {
    asm("mov.b64 {%0, %1}, %2;" : "=f"(x), "=f"(y) : "l"(v));
}
__device__ __forceinline__ ull ffma2(ull a, ull b, ull c) {
    ull d; asm("fma.rn.f32x2 %0, %1, %2, %3;" : "=l"(d) : "l"(a), "l"(b), "l"(c)); return d;
}
__device__ __forceinline__ ull fmul2(ull a, ull b) {
    ull d; asm("mul.rn.f32x2 %0, %1, %2;" : "=l"(d) : "l"(a), "l"(b)); return d;
}
__device__ __forceinline__ ull fadd2(ull a, ull b) {
    ull d; asm("add.rn.f32x2 %0, %1, %2;" : "=l"(d) : "l"(a), "l"(b)); return d;
}
__device__ __forceinline__ float fast_exp_scaled(float y) {   // exp(x), y = x*log2e
    const float BIG = 12582912.0f;
    float t = y + BIG;
    float nf = t - BIG;
    float r = y - nf;
    float p = fmaf(0.00133335581f, r, 0.00961812911f);
    p = fmaf(p, r, 0.0555041087f);
    p = fmaf(p, r, 0.240226507f);
    p = fmaf(p, r, 0.693147182f);
    p = fmaf(p, r, 1.0f);
    return __int_as_float(__float_as_int(p) + (__float_as_int(t) << 23));
}

// ---------------------------------------------------------------------------
// mma.sync / ldmatrix / cp.async wrappers (baseline PTX, plain sm_103 target)
// ---------------------------------------------------------------------------
__device__ __forceinline__ u32 smem_u32(const void* p) {
    u32 a; asm("{ .reg .u64 t; cvta.to.shared.u64 t, %1; cvt.u32.u64 %0, t; }"
               : "=r"(a) : "l"(p));
    return a;
}
__device__ __forceinline__ void ldmx4(u32& r0, u32& r1, u32& r2, u32& r3, u32 a) {
    asm volatile("ldmatrix.sync.aligned.m8n8.x4.shared.b16 {%0,%1,%2,%3}, [%4];"
                 : "=r"(r0), "=r"(r1), "=r"(r2), "=r"(r3) : "r"(a));
}
__device__ __forceinline__ void mma16816(float* c, const u32* a, u32 b0, u32 b1) {
    asm volatile(
        "mma.sync.aligned.m16n8k16.row.col.f32.bf16.bf16.f32 "
        "{%0,%1,%2,%3}, {%4,%5,%6,%7}, {%8,%9}, {%0,%1,%2,%3};"
        : "+f"(c[0]), "+f"(c[1]), "+f"(c[2]), "+f"(c[3])
        : "r"(a[0]), "r"(a[1]), "r"(a[2]), "r"(a[3]), "r"(b0), "r"(b1));
}
__device__ __forceinline__ void cp_async16(u32 dst, const void* src) {
    asm volatile("cp.async.cg.shared.global [%0], [%1], 16;"
                 :: "r"(dst), "l"(src));
}
__device__ __forceinline__ void cp_async_commit_wait() {
    asm volatile("cp.async.commit_group;");
    asm volatile("cp.async.wait_group 0;");
}

// ---------------------------------------------------------------------------
// Kernel 0: transpose + bf16 hi/lo split of W and Wo (B operands, n-major).
// ---------------------------------------------------------------------------
__global__ void prep_weights(const float* __restrict__ W, const float* __restrict__ Wo)
{
    const int i = blockIdx.x * 256 + threadIdx.x;  // 0..16383
    if (i < 12288) {                 // W[k][n], k<64, n<192
        const int k = i / 192, n = i % 192;
        const float v = W[i];
        const u16 h = f2bf(v);
        const u16 l = f2bf(v - bf2f(h));
        g_wq[n * 72 + k] = h;
        g_wq[192 * 72 + n * 72 + k] = l;
    } else {                         // Wo[k][n], k<64, n<64
        const int j = i - 12288;
        const int k = j / 64, n = j % 64;
        const float v = Wo[j];
        const u16 h = f2bf(v);
        const u16 l = f2bf(v - bf2f(h));
        g_wo[n * 72 + k] = h;
        g_wo[64 * 72 + n * 72 + k] = l;
    }
}

// ---------------------------------------------------------------------------
// Kernel 1: QKV = X @ W via mma.sync bf16-split. CTA: 64 rows x 192 cols.
// cp.async W stage overlaps the X split transform. occ 3.
// ---------------------------------------------------------------------------
#define QK_XH 0
#define QK_XL 9216
#define QK_W  18432
#define QK_SMEM (18432 + 55296)   // 73728

__global__ __launch_bounds__(256, 3)
void qkv_mma(const float* __restrict__ X, float* __restrict__ out)
{
    extern __shared__ char sm[];
    const u32 sb = smem_u32(sm);
    const int tid = threadIdx.x;
    const size_t row0 = (size_t)blockIdx.x * 64;

    // async-stage W hi+lo (55296B) while we transform X
    {
        const char* src = (const char*)g_wq;
        for (int i = tid; i < 3456; i += 256)
            cp_async16(sb + QK_W + i * 16, src + i * 16);
        asm volatile("cp.async.commit_group;");
    }
    // stage X split (64x64 fp32 -> Xh/Xl [64][72] bf16)
    {
        const float4* xs = (const float4*)(X + row0 * EE);
        for (int i = tid; i < 1024; i += 256) {
            float4 v = xs[i];
            const int r = i >> 4, k = (i & 15) * 4;
            u16 h0 = f2bf(v.x), h1 = f2bf(v.y), h2 = f2bf(v.z), h3 = f2bf(v.w);
            ushort4 H; H.x = h0; H.y = h1; H.z = h2; H.w = h3;
            ushort4 L;
            L.x = f2bf(v.x - bf2f(h0)); L.y = f2bf(v.y - bf2f(h1));
            L.z = f2bf(v.z - bf2f(h2)); L.w = f2bf(v.w - bf2f(h3));
            *(ushort4*)(sm + QK_XH + (r * 72 + k) * 2) = H;
            *(ushort4*)(sm + QK_XL + (r * 72 + k) * 2) = L;
        }
    }
    asm volatile("cp.async.wait_group 0;");
    __syncthreads();

    const int lane = tid & 31;
    const int wid  = tid >> 5;
    const int rg = (wid & 1) * 32;    // warp row base (within 64)
    const int cg = (wid >> 1) * 48;   // warp col base (within 192)

    const int grp = lane >> 3;
    const u32 a_base = sb + QK_XH +
        (u32)((rg + (grp & 1) * 8 + (lane & 7)) * 144 + (grp >> 1) * 16);
    const u32 b_base = sb + QK_W +
        (u32)((cg + (grp >> 1) * 8 + (lane & 7)) * 144 + (grp & 1) * 16);
    const u32 XLOFF = 9216;
    const u32 WLOFF = 27648;

    float acc[2][6][4];
    #pragma unroll
    for (int m = 0; m < 2; m++)
        #pragma unroll
        for (int j = 0; j < 6; j++)
            #pragma unroll
            for (int q = 0; q < 4; q++) acc[m][j][q] = 0.f;

    #pragma unroll
    for (int ks = 0; ks < 4; ks++) {
        const u32 kb = (u32)(ks * 32);
        u32 Ah[2][4], Al[2][4];
        ldmx4(Ah[0][0], Ah[0][1], Ah[0][2], Ah[0][3], a_base + kb);
        ldmx4(Ah[1][0], Ah[1][1], Ah[1][2], Ah[1][3], a_base + 2304 + kb);
        ldmx4(Al[0][0], Al[0][1], Al[0][2], Al[0][3], a_base + XLOFF + kb);
        ldmx4(Al[1][0], Al[1][1], Al[1][2], Al[1][3], a_base + XLOFF + 2304 + kb);

        #pragma unroll
        for (int jp = 0; jp < 3; jp++) {
            u32 Bh[4], Bl[4];
            const u32 bo = b_base + (u32)(jp * 2304) + kb;
            ldmx4(Bh[0], Bh[1], Bh[2], Bh[3], bo);
            ldmx4(Bl[0], Bl[1], Bl[2], Bl[3], bo + WLOFF);
            #pragma unroll
            for (int m = 0; m < 2; m++)
                #pragma unroll
                for (int js = 0; js < 2; js++) {
                    float* a = acc[m][jp * 2 + js];
                    mma16816(a, Ah[m], Bh[js * 2], Bh[js * 2 + 1]);
                    mma16816(a, Ah[m], Bl[js * 2], Bl[js * 2 + 1]);
                    mma16816(a, Al[m], Bh[js * 2], Bh[js * 2 + 1]);
                }
        }
    }

    #pragma unroll
    for (int m = 0; m < 2; m++) {
        const size_t r = row0 + rg + m * 16 + (lane >> 2);
        #pragma unroll
        for (int j = 0; j < 6; j++) {
            const int c = cg + 8 * j + 2 * (lane & 3);
            float2 v0; v0.x = acc[m][j][0]; v0.y = acc[m][j][1];
            float2 v1; v1.x = acc[m][j][2]; v1.y = acc[m][j][3];
            *(float2*)(out + r * C3U + c)       = v0;
            *(float2*)(out + (r + 8) * C3U + c) = v1;
        }
    }
}

// ---------------------------------------------------------------------------
// Kernel 2: attention per (b,h). SIMT f32x2, q pre-scaled by 0.25*log2(e).
// ---------------------------------------------------------------------------
__global__ __launch_bounds__(224, 4)
void attn_kernel(const float* __restrict__ qkv, const int* __restrict__ lens,
                 float* __restrict__ out)
{
    const int b = blockIdx.x;
    const int h = blockIdx.y;

    __shared__ __align__(16) float Ks[TT][DH];
    __shared__ __align__(16) float Vs[TT][DH];

    const float* base = qkv + (size_t)b * TT * C3U;
    const int tid = threadIdx.x;

    for (int i = tid; i < TT * 4; i += 224) {
        const int k  = i >> 2;
        const int d4 = i & 3;
        ((float4*)&Ks[k][0])[d4] = ((const float4*)(base + (size_t)k * C3U + UU     + h * DH))[d4];
        ((float4*)&Vs[k][0])[d4] = ((const float4*)(base + (size_t)k * C3U + 2 * UU + h * DH))[d4];
    }
    __syncthreads();

    const int t = tid;
    if (t >= TT) return;

    const float CSC = 0.36067376022224085f;   // 0.25 * log2(e)
    ull q2[8];
    {
        const float2* qp = (const float2*)(base + (size_t)t * C3U + h * DH);
        #pragma unroll
        for (int i = 0; i < 8; i++) {
            float2 qv = qp[i];
            q2[i] = pack2(qv.x * CSC, qv.y * CSC);   // fold scale into q
        }
    }

    int len = lens[b];
    if (len < 1) len = 1;
    if (len > TT) len = TT;

    const float BIG = 12582912.0f;
    const ull BIG2  = pack2(BIG, BIG);
    const ull NBIG2 = pack2(-BIG, -BIG);
    const ull MONE2 = pack2(-1.0f, -1.0f);
    const ull C5_2  = pack2(0.00133335581f, 0.00133335581f);
    const ull C4_2  = pack2(0.00961812911f, 0.00961812911f);
    const ull C3_2  = pack2(0.0555041087f, 0.0555041087f);
    const ull C2_2  = pack2(0.240226507f, 0.240226507f);
    const ull C1_2  = pack2(0.693147182f, 0.693147182f);
    const ull ONE2  = pack2(1.0f, 1.0f);

    ull l2 = 0ull;
    ull o2[8];
    #pragma unroll
    for (int i = 0; i < 8; i++) o2[i] = 0ull;

    int k = 0;
    for (; k + 2 <= len; k += 2) {
        const ulonglong2* kpa = (const ulonglong2*)&Ks[k][0];
        const ulonglong2* kpb = (const ulonglong2*)&Ks[k + 1][0];
        ulonglong2 a0 = kpa[0], a1 = kpa[1], a2v = kpa[2], a3 = kpa[3];
        ulonglong2 b0 = kpb[0], b1 = kpb[1], b2v = kpb[2], b3 = kpb[3];

        ull da0 = fmul2(q2[0], a0.x);
        ull da1 = fmul2(q2[1], a0.y);
        ull db0 = fmul2(q2[0], b0.x);
        ull db1 = fmul2(q2[1], b0.y);
        da0 = ffma2(q2[2], a1.x, da0);
        da1 = ffma2(q2[3], a1.y, da1);
        db0 = ffma2(q2[2], b1.x, db0);
        db1 = ffma2(q2[3], b1.y, db1);
        da0 = ffma2(q2[4], a2v.x, da0);
        da1 = ffma2(q2[5], a2v.y, da1);
        db0 = ffma2(q2[4], b2v.x, db0);
        db1 = ffma2(q2[5], b2v.y, db1);
        da0 = ffma2(q2[6], a3.x, da0);
        da1 = ffma2(q2[7], a3.y, da1);
        db0 = ffma2(q2[6], b3.x, db0);
        db1 = ffma2(q2[7], b3.y, db1);

        float sa0, sa1, sb0, sb1;
        unpack2(fadd2(da0, da1), sa0, sa1);
        unpack2(fadd2(db0, db1), sb0, sb1);
        ull y2 = pack2(sa0 + sa1, sb0 + sb1);   // already log2-scaled

        ull t2  = fadd2(y2, BIG2);
        ull nf2 = fadd2(t2, NBIG2);
        ull r2  = ffma2(nf2, MONE2, y2);
        ull p2  = ffma2(C5_2, r2, C4_2);
        p2 = ffma2(p2, r2, C3_2);
        p2 = ffma2(p2, r2, C2_2);
        p2 = ffma2(p2, r2, C1_2);
        p2 = ffma2(p2, r2, ONE2);
        float pa, pb, ta, tb;
        unpack2(p2, pa, pb);
        unpack2(t2, ta, tb);
        const float e0 = __int_as_float(__float_as_int(pa) + (__float_as_int(ta) << 23));
        const float e1 = __int_as_float(__float_as_int(pb) + (__float_as_int(tb) << 23));
        l2 = fadd2(l2, pack2(e0, e1));

        const ull pk0 = pack2(e0, e0);
        const ull pk1 = pack2(e1, e1);
        const ulonglong2* vpa = (const ulonglong2*)&Vs[k][0];
        const ulonglong2* vpb = (const ulonglong2*)&Vs[k + 1][0];
        ulonglong2 va0 = vpa[0], va1 = vpa[1], va2 = vpa[2], va3 = vpa[3];
        ulonglong2 vb0 = vpb[0], vb1 = vpb[1], vb2 = vpb[2], vb3 = vpb[3];
        o2[0] = ffma2(pk0, va0.x, o2[0]);
        o2[1] = ffma2(pk0, va0.y, o2[1]);
        o2[2] = ffma2(pk0, va1.x, o2[2]);
        o2[3] = ffma2(pk0, va1.y, o2[3]);
        o2[4] = ffma2(pk0, va2.x, o2[4]);
        o2[5] = ffma2(pk0, va2.y, o2[5]);
        o2[6] = ffma2(pk0, va3.x, o2[6]);
        o2[7] = ffma2(pk0, va3.y, o2[7]);
        o2[0] = ffma2(pk1, vb0.x, o2[0]);
        o2[1] = ffma2(pk1, vb0.y, o2[1]);
        o2[2] = ffma2(pk1, vb1.x, o2[2]);
        o2[3] = ffma2(pk1, vb1.y, o2[3]);
        o2[4] = ffma2(pk1, vb2.x, o2[4]);
        o2[5] = ffma2(pk1, vb2.y, o2[5]);
        o2[6] = ffma2(pk1, vb3.x, o2[6]);
        o2[7] = ffma2(pk1, vb3.y, o2[7]);
    }
    if (k < len) {
        const ulonglong2* kp = (const ulonglong2*)&Ks[k][0];
        ulonglong2 a0 = kp[0], a1 = kp[1], a2v = kp[2], a3 = kp[3];
        ull d0 = fmul2(q2[0], a0.x);
        ull d1 = fmul2(q2[1], a0.y);
        d0 = ffma2(q2[2], a1.x, d0);
        d1 = ffma2(q2[3], a1.y, d1);
        d0 = ffma2(q2[4], a2v.x, d0);
        d1 = ffma2(q2[5], a2v.y, d1);
        d0 = ffma2(q2[6], a3.x, d0);
        d1 = ffma2(q2[7], a3.y, d1);
        float s0, s1;
        unpack2(fadd2(d0, d1), s0, s1);
        const float p = fast_exp_scaled(s0 + s1);
        l2 = fadd2(l2, pack2(p, 0.f));
        const ull pk = pack2(p, p);
        const ulonglong2* vp = (const ulonglong2*)&Vs[k][0];
        ulonglong2 v0 = vp[0], v1 = vp[1], v2 = vp[2], v3 = vp[3];
        o2[0] = ffma2(pk, v0.x, o2[0]);
        o2[1] = ffma2(pk, v0.y, o2[1]);
        o2[2] = ffma2(pk, v1.x, o2[2]);
        o2[3] = ffma2(pk, v1.y, o2[3]);
        o2[4] = ffma2(pk, v2.x, o2[4]);
        o2[5] = ffma2(pk, v2.y, o2[5]);
        o2[6] = ffma2(pk, v3.x, o2[6]);
        o2[7] = ffma2(pk, v3.y, o2[7]);
    }

    float lA, lB;
    unpack2(l2, lA, lB);
    const float inv = 1.0f / (lA + lB);
    float* orow = out + ((size_t)b * TT + t) * UU + h * DH;
    #pragma unroll
    for (int i = 0; i < 4; i++) {
        float v0, v1, w0, w1;
        unpack2(o2[2 * i],     v0, v1);
        unpack2(o2[2 * i + 1], w0, w1);
        float4 o;
        o.x = v0 * inv; o.y = v1 * inv; o.z = w0 * inv; o.w = w1 * inv;
        ((float4*)orow)[i] = o;
    }
}

// ---------------------------------------------------------------------------
// Kernel 3: Y = A @ Wo (mma.sync bf16-split) + X; LN(64) IN-REGISTER on
// fragments (row lives in a lane-quad; shfl_xor 1,2 reduces mean/var).
// CTA: 128 rows, 8 warps, each 16 rows x 64 cols. occ 3.
// ---------------------------------------------------------------------------
#define PJ_AH 0
#define PJ_AL 18432
#define PJ_W  36864
#define PJ_SMEM (36864 + 18432)   // 55296

__global__ __launch_bounds__(256, 3)
void proj_mma(const float* __restrict__ A, const float* __restrict__ X,
              const float* __restrict__ gamma, const float* __restrict__ beta,
              float* __restrict__ out)
{
    extern __shared__ char sm[];
    const u32 sb = smem_u32(sm);
    const int tid = threadIdx.x;
    const size_t row0 = (size_t)blockIdx.x * 128;

    // async-stage Wo hi+lo (18432B)
    {
        const char* src = (const char*)g_wo;
        for (int i = tid; i < 1152; i += 256)
            cp_async16(sb + PJ_W + i * 16, src + i * 16);
        asm volatile("cp.async.commit_group;");
    }
    // stage A split (128x64 fp32 -> Ah/Al [128][72] bf16)
    {
        const float4* as = (const float4*)(A + row0 * UU);
        for (int i = tid; i < 2048; i += 256) {
            float4 v = as[i];
            const int r = i >> 4, k = (i & 15) * 4;
            u16 h0 = f2bf(v.x), h1 = f2bf(v.y), h2 = f2bf(v.z), h3 = f2bf(v.w);
            ushort4 H; H.x = h0; H.y = h1; H.z = h2; H.w = h3;
            ushort4 L;
            L.x = f2bf(v.x - bf2f(h0)); L.y = f2bf(v.y - bf2f(h1));
            L.z = f2bf(v.z - bf2f(h2)); L.w = f2bf(v.w - bf2f(h3));
            *(ushort4*)(sm + PJ_AH + (r * 72 + k) * 2) = H;
            *(ushort4*)(sm + PJ_AL + (r * 72 + k) * 2) = L;
        }
    }
    asm volatile("cp.async.wait_group 0;");
    __syncthreads();

    const int lane = tid & 31;
    const int wid  = tid >> 5;
    const int rg = wid * 16;

    const int grp = lane >> 3;
    const u32 a_base = sb + PJ_AH +
        (u32)((rg + (grp & 1) * 8 + (lane & 7)) * 144 + (grp >> 1) * 16);
    const u32 b_base = sb + PJ_W +
        (u32)(((grp >> 1) * 8 + (lane & 7)) * 144 + (grp & 1) * 16);
    const u32 ALOFF = 18432;
    const u32 WLOFF = 9216;

    float acc[8][4];
    #pragma unroll
    for (int j = 0; j < 8; j++)
        #pragma unroll
        for (int q = 0; q < 4; q++) acc[j][q] = 0.f;

    #pragma unroll
    for (int ks = 0; ks < 4; ks++) {
        const u32 kb = (u32)(ks * 32);
        u32 Ah[4], Al[4];
        ldmx4(Ah[0], Ah[1], Ah[2], Ah[3], a_base + kb);
        ldmx4(Al[0], Al[1], Al[2], Al[3], a_base + ALOFF + kb);

        #pragma unroll
        for (int jp = 0; jp < 4; jp++) {
            u32 Bh[4], Bl[4];
            const u32 bo = b_base + (u32)(jp * 2304) + kb;
            ldmx4(Bh[0], Bh[1], Bh[2], Bh[3], bo);
            ldmx4(Bl[0], Bl[1], Bl[2], Bl[3], bo + WLOFF);
            #pragma unroll
            for (int js = 0; js < 2; js++) {
                float* a = acc[jp * 2 + js];
                mma16816(a, Ah, Bh[js * 2], Bh[js * 2 + 1]);
                mma16816(a, Ah, Bl[js * 2], Bl[js * 2 + 1]);
                mma16816(a, Al, Bh[js * 2], Bh[js * 2 + 1]);
            }
        }
    }

    // ---- in-register residual + LN ----
    const size_t rowA = row0 + rg + (lane >> 2);
    const size_t rowB = rowA + 8;
    const int cq = 2 * (lane & 3);

    // residual add
    #pragma unroll
    for (int j = 0; j < 8; j++) {
        const int c = 8 * j + cq;
        float2 xa = *(const float2*)(X + rowA * UU + c);
        float2 xb = *(const float2*)(X + rowB * UU + c);
        acc[j][0] += xa.x; acc[j][1] += xa.y;
        acc[j][2] += xb.x; acc[j][3] += xb.y;
    }

    // mean over 64 cols (lane-quad holds the row)
    float sA = 0.f, sB = 0.f;
    #pragma unroll
    for (int j = 0; j < 8; j++) {
        sA += acc[j][0] + acc[j][1];
        sB += acc[j][2] + acc[j][3];
    }
    sA += __shfl_xor_sync(0xFFFFFFFFu, sA, 1);
    sA += __shfl_xor_sync(0xFFFFFFFFu, sA, 2);
    sB += __shfl_xor_sync(0xFFFFFFFFu, sB, 1);
    sB += __shfl_xor_sync(0xFFFFFFFFu, sB, 2);
    const float mA = sA * (1.0f / 64.0f);
    const float mB = sB * (1.0f / 64.0f);

    float vA = 0.f, vB = 0.f;
    #pragma unroll
    for (int j = 0; j < 8; j++) {
        float d0 = acc[j][0] - mA, d1 = acc[j][1] - mA;
        float d2 = acc[j][2] - mB, d3 = acc[j][3] - mB;
        vA = fmaf(d0, d0, fmaf(d1, d1, vA));
        vB = fmaf(d2, d2, fmaf(d3, d3, vB));
    }
    vA += __shfl_xor_sync(0xFFFFFFFFu, vA, 1);
    vA += __shfl_xor_sync(0xFFFFFFFFu, vA, 2);
    vB += __shfl_xor_sync(0xFFFFFFFFu, vB, 1);
    vB += __shfl_xor_sync(0xFFFFFFFFu, vB, 2);
    const float iA = rsqrtf(vA * (1.0f / 64.0f) + 1e-9f);
    const float iB = rsqrtf(vB * (1.0f / 64.0f) + 1e-9f);

    #pragma unroll
    for (int j = 0; j < 8; j++) {
        const int c = 8 * j + cq;
        const float2 gg = *(const float2*)(gamma + c);
        const float2 bb = *(const float2*)(beta + c);
        float2 oa, ob;
        oa.x = fmaf((acc[j][0] - mA) * iA, gg.x, bb.x);
        oa.y = fmaf((acc[j][1] - mA) * iA, gg.y, bb.y);
        ob.x = fmaf((acc[j][2] - mB) * iB, gg.x, bb.x);
        ob.y = fmaf((acc[j][3] - mB) * iB, gg.y, bb.y);
        *(float2*)(out + rowA * UU + c) = oa;
        *(float2*)(out + rowB * UU + c) = ob;
    }
}

// ---------------------------------------------------------------------------
extern "C" void kernel_launch(void* const* d_in, const int* in_sizes, int n_in,
                              void* d_out, int out_size)
{
    const float* input_info = (const float*)d_in[0];
    const int*   keys_len   = (const int*)d_in[1];
    const float* W          = (const float*)d_in[2];
    const float* W_output   = (const float*)d_in[3];
    const float* gamma      = (const float*)d_in[4];
    const float* beta       = (const float*)d_in[5];
    float* out = (float*)d_out;

    float* qkv;  cudaGetSymbolAddress((void**)&qkv,  g_qkv);
    float* attn; cudaGetSymbolAddress((void**)&attn, g_attn);

    cudaFuncSetAttribute(qkv_mma,  cudaFuncAttributeMaxDynamicSharedMemorySize, QK_SMEM);
    cudaFuncSetAttribute(proj_mma, cudaFuncAttributeMaxDynamicSharedMemorySize, PJ_SMEM);

    prep_weights<<<64, 256>>>(W, W_output);

    qkv_mma<<<(BB * TT) / 64, 256, QK_SMEM>>>(input_info, qkv);

    dim3 g2(BB, HH);
    attn_kernel<<<g2, 224>>>(qkv, keys_len, attn);

    proj_mma<<<(BB * TT) / 128, 256, PJ_SMEM>>>(attn, input_info, gamma, beta, out);
}

// round 8
// speedup vs baseline: 1.5139x; 1.5139x over previous
#include <cuda_runtime.h>
#include <math.h>

#define BB 1024
#define TT 200
#define EE 64
#define UU 64
#define HH 4
#define DH 16
#define C3U 192

typedef unsigned long long ull;
typedef unsigned int u32;
typedef unsigned short u16;

__device__ float g_qkv[(size_t)BB * TT * C3U];
__device__ float g_attn[(size_t)BB * TT * UU];
__device__ __align__(16) u16 g_wq[2 * 192 * 72];
__device__ __align__(16) u16 g_wo[2 * 64 * 72];

// ---------------------------------------------------------------------------
__device__ __forceinline__ u16 f2bf(float f) {
    u32 u = __float_as_uint(f);
    u32 r = u + 0x7FFFu + ((u >> 16) & 1u);
    return (u16)(r >> 16);
}
__device__ __forceinline__ float bf2f(u16 b) {
    return __uint_as_float(((u32)b) << 16);
}
__device__ __forceinline__ ull pack2(float x, float y) {
    ull r; asm("mov.b64 %0, {%1, %2};" : "=l"(r) : "f"(x), "f"(y)); return r;
}
__device__ __forceinline__ void unpack2(ull v, float& x, float& y) {
    asm("mov.b64 {%0, %1}, %2;" : "=f"(x), "=f"(y) : "l"(v));
}
__device__ __forceinline__ ull ffma2(ull a, ull b, ull c) {
    ull d; asm("fma.rn.f32x2 %0, %1, %2, %3;" : "=l"(d) : "l"(a), "l"(b), "l"(c)); return d;
}
__device__ __forceinline__ ull fmul2(ull a, ull b) {
    ull d; asm("mul.rn.f32x2 %0, %1, %2;" : "=l"(d) : "l"(a), "l"(b)); return d;
}
__device__ __forceinline__ ull fadd2(ull a, ull b) {
    ull d; asm("add.rn.f32x2 %0, %1, %2;" : "=l"(d) : "l"(a), "l"(b)); return d;
}

// packed 2^y (y already log2-scaled)
__device__ __forceinline__ ull exp2p(ull y2) {
    const float BIG = 12582912.0f;
    ull t2  = fadd2(y2, pack2(BIG, BIG));
    ull nf2 = fadd2(t2, pack2(-BIG, -BIG));
    ull r2  = ffma2(nf2, pack2(-1.f, -1.f), y2);
    ull p2  = ffma2(pack2(0.00133335581f, 0.00133335581f), r2,
                    pack2(0.00961812911f, 0.00961812911f));
    p2 = ffma2(p2, r2, pack2(0.0555041087f, 0.0555041087f));
    p2 = ffma2(p2, r2, pack2(0.240226507f, 0.240226507f));
    p2 = ffma2(p2, r2, pack2(0.693147182f, 0.693147182f));
    p2 = ffma2(p2, r2, pack2(1.f, 1.f));
    float pa, pb, ta, tb;
    unpack2(p2, pa, pb);
    unpack2(t2, ta, tb);
    const float e0 = __int_as_float(__float_as_int(pa) + (__float_as_int(ta) << 23));
    const float e1 = __int_as_float(__float_as_int(pb) + (__float_as_int(tb) << 23));
    return pack2(e0, e1);
}
__device__ __forceinline__ u32 cvt_bf16x2p(ull e2) {
    float x, y; unpack2(e2, x, y);
    u32 r; asm("cvt.rn.bf16x2.f32 %0, %1, %2;" : "=r"(r) : "f"(y), "f"(x));
    return r;
}

// ---------------------------------------------------------------------------
__device__ __forceinline__ u32 smem_u32(const void* p) {
    u32 a; asm("{ .reg .u64 t; cvta.to.shared.u64 t, %1; cvt.u32.u64 %0, t; }"
               : "=r"(a) : "l"(p));
    return a;
}
__device__ __forceinline__ void ldmx4(u32& r0, u32& r1, u32& r2, u32& r3, u32 a) {
    asm volatile("ldmatrix.sync.aligned.m8n8.x4.shared.b16 {%0,%1,%2,%3}, [%4];"
                 : "=r"(r0), "=r"(r1), "=r"(r2), "=r"(r3) : "r"(a));
}
__device__ __forceinline__ void mma16816(float* c, const u32* a, u32 b0, u32 b1) {
    asm volatile(
        "mma.sync.aligned.m16n8k16.row.col.f32.bf16.bf16.f32 "
        "{%0,%1,%2,%3}, {%4,%5,%6,%7}, {%8,%9}, {%0,%1,%2,%3};"
        : "+f"(c[0]), "+f"(c[1]), "+f"(c[2]), "+f"(c[3])
        : "r"(a[0]), "r"(a[1]), "r"(a[2]), "r"(a[3]), "r"(b0), "r"(b1));
}
__device__ __forceinline__ void cp_async16(u32 dst, const void* src) {
    asm volatile("cp.async.cg.shared.global [%0], [%1], 16;" :: "r"(dst), "l"(src));
}

// ---------------------------------------------------------------------------
__global__ void prep_weights(const float* __restrict__ W, const float* __restrict__ Wo)
{
    const int i = blockIdx.x * 256 + threadIdx.x;
    if (i < 12288) {
        const int k = i / 192, n = i % 192;
        const float v = W[i];
        const u16 h = f2bf(v);
        g_wq[n * 72 + k] = h;
        g_wq[192 * 72 + n * 72 + k] = f2bf(v - bf2f(h));
    } else {
        const int j = i - 12288;
        const int k = j / 64, n = j % 64;
        const float v = Wo[j];
        const u16 h = f2bf(v);
        g_wo[n * 72 + k] = h;
        g_wo[64 * 72 + n * 72 + k] = f2bf(v - bf2f(h));
    }
}

// ---------------------------------------------------------------------------
// Kernel 1: QKV = X @ W (unchanged, proven)
// ---------------------------------------------------------------------------
#define QK_XH 0
#define QK_XL 9216
#define QK_W  18432
#define QK_SMEM (18432 + 55296)

__global__ __launch_bounds__(256, 3)
void qkv_mma(const float* __restrict__ X, float* __restrict__ out)
{
    extern __shared__ char sm[];
    const u32 sb = smem_u32(sm);
    const int tid = threadIdx.x;
    const size_t row0 = (size_t)blockIdx.x * 64;

    {
        const char* src = (const char*)g_wq;
        for (int i = tid; i < 3456; i += 256)
            cp_async16(sb + QK_W + i * 16, src + i * 16);
        asm volatile("cp.async.commit_group;");
    }
    {
        const float4* xs = (const float4*)(X + row0 * EE);
        for (int i = tid; i < 1024; i += 256) {
            float4 v = xs[i];
            const int r = i >> 4, k = (i & 15) * 4;
            u16 h0 = f2bf(v.x), h1 = f2bf(v.y), h2 = f2bf(v.z), h3 = f2bf(v.w);
            ushort4 H; H.x = h0; H.y = h1; H.z = h2; H.w = h3;
            ushort4 L;
            L.x = f2bf(v.x - bf2f(h0)); L.y = f2bf(v.y - bf2f(h1));
            L.z = f2bf(v.z - bf2f(h2)); L.w = f2bf(v.w - bf2f(h3));
            *(ushort4*)(sm + QK_XH + (r * 72 + k) * 2) = H;
            *(ushort4*)(sm + QK_XL + (r * 72 + k) * 2) = L;
        }
    }
    asm volatile("cp.async.wait_group 0;");
    __syncthreads();

    const int lane = tid & 31;
    const int wid  = tid >> 5;
    const int rg = (wid & 1) * 32;
    const int cg = (wid >> 1) * 48;
    const int grp = lane >> 3;
    const u32 a_base = sb + QK_XH +
        (u32)((rg + (grp & 1) * 8 + (lane & 7)) * 144 + (grp >> 1) * 16);
    const u32 b_base = sb + QK_W +
        (u32)((cg + (grp >> 1) * 8 + (lane & 7)) * 144 + (grp & 1) * 16);
    const u32 XLOFF = 9216, WLOFF = 27648;

    float acc[2][6][4];
    #pragma unroll
    for (int m = 0; m < 2; m++)
        #pragma unroll
        for (int j = 0; j < 6; j++)
            #pragma unroll
            for (int q = 0; q < 4; q++) acc[m][j][q] = 0.f;

    #pragma unroll
    for (int ks = 0; ks < 4; ks++) {
        const u32 kb = (u32)(ks * 32);
        u32 Ah[2][4], Al[2][4];
        ldmx4(Ah[0][0], Ah[0][1], Ah[0][2], Ah[0][3], a_base + kb);
        ldmx4(Ah[1][0], Ah[1][1], Ah[1][2], Ah[1][3], a_base + 2304 + kb);
        ldmx4(Al[0][0], Al[0][1], Al[0][2], Al[0][3], a_base + XLOFF + kb);
        ldmx4(Al[1][0], Al[1][1], Al[1][2], Al[1][3], a_base + XLOFF + 2304 + kb);
        #pragma unroll
        for (int jp = 0; jp < 3; jp++) {
            u32 Bh[4], Bl[4];
            const u32 bo = b_base + (u32)(jp * 2304) + kb;
            ldmx4(Bh[0], Bh[1], Bh[2], Bh[3], bo);
            ldmx4(Bl[0], Bl[1], Bl[2], Bl[3], bo + WLOFF);
            #pragma unroll
            for (int m = 0; m < 2; m++)
                #pragma unroll
                for (int js = 0; js < 2; js++) {
                    float* a = acc[m][jp * 2 + js];
                    mma16816(a, Ah[m], Bh[js * 2], Bh[js * 2 + 1]);
                    mma16816(a, Ah[m], Bl[js * 2], Bl[js * 2 + 1]);
                    mma16816(a, Al[m], Bh[js * 2], Bh[js * 2 + 1]);
                }
        }
    }

    #pragma unroll
    for (int m = 0; m < 2; m++) {
        const size_t r = row0 + rg + m * 16 + (lane >> 2);
        #pragma unroll
        for (int j = 0; j < 6; j++) {
            const int c = cg + 8 * j + 2 * (lane & 3);
            float2 v0; v0.x = acc[m][j][0]; v0.y = acc[m][j][1];
            float2 v1; v1.x = acc[m][j][2]; v1.y = acc[m][j][3];
            *(float2*)(out + r * C3U + c)       = v0;
            *(float2*)(out + (r + 8) * C3U + c) = v1;
        }
    }
}

// ---------------------------------------------------------------------------
// Kernel 2: FA2-style HMMA attention. One CTA per (b,h), 7 warps x 2 m-tiles.
// ---------------------------------------------------------------------------
#define AT_QH  0
#define AT_QL  9984
#define AT_KH  19968
#define AT_KL  29952
#define AT_VTH 39936
#define AT_VTL 46848
#define AT_SMEM 53760

#define SPLIT2(vx, vy, HI, LO) { \
    u16 _hx = f2bf(vx), _hy = f2bf(vy); \
    HI = (u32)_hx | ((u32)_hy << 16); \
    LO = (u32)f2bf((vx) - bf2f(_hx)) | ((u32)f2bf((vy) - bf2f(_hy)) << 16); }

__device__ __forceinline__ void attn_store(float* po, int mt, int lane,
                                           const float* oA, const float* oB,
                                           ull lA, ull lB)
{
    float x, y;
    unpack2(lA, x, y); float la = x + y;
    la += __shfl_xor_sync(0xFFFFFFFFu, la, 1);
    la += __shfl_xor_sync(0xFFFFFFFFu, la, 2);
    unpack2(lB, x, y); float lb = x + y;
    lb += __shfl_xor_sync(0xFFFFFFFFu, lb, 1);
    lb += __shfl_xor_sync(0xFFFFFFFFu, lb, 2);
    const float iA = 1.f / la, iB = 1.f / lb;
    const int cb = 2 * (lane & 3);
    const int rA = mt * 16 + (lane >> 2), rB = rA + 8;
    if (rA < TT) {
        float2 t;
        t.x = oA[0] * iA; t.y = oA[1] * iA; *(float2*)(po + (size_t)rA * UU + cb) = t;
        t.x = oB[0] * iA; t.y = oB[1] * iA; *(float2*)(po + (size_t)rA * UU + 8 + cb) = t;
    }
    if (rB < TT) {
        float2 t;
        t.x = oA[2] * iB; t.y = oA[3] * iB; *(float2*)(po + (size_t)rB * UU + cb) = t;
        t.x = oB[2] * iB; t.y = oB[3] * iB; *(float2*)(po + (size_t)rB * UU + 8 + cb) = t;
    }
}

__global__ __launch_bounds__(224, 2)
void attn_mma(const float* __restrict__ qkv, const int* __restrict__ lens,
              float* __restrict__ out)
{
    extern __shared__ char sm[];
    const u32 sb = smem_u32(sm);
    const int tid = threadIdx.x;
    const int b = blockIdx.x, h = blockIdx.y;
    const float* base = qkv + (size_t)b * TT * C3U;

    int len = lens[b];
    if (len < 1) len = 1;
    if (len > TT) len = TT;
    const int kcnt = (len + 15) >> 4;
    const float CSC = 0.36067376022224085f;   // 0.25 * log2(e)

    if (tid < TT) {
        const size_t ro = (size_t)tid * C3U + h * DH;
        const float4* q4 = (const float4*)(base + ro);
        const float4* k4 = (const float4*)(base + ro + UU);
        const float4* v4 = (const float4*)(base + ro + 2 * UU);
        float4 qv[4] = {q4[0], q4[1], q4[2], q4[3]};
        float4 kv[4] = {k4[0], k4[1], k4[2], k4[3]};
        #pragma unroll
        for (int j = 0; j < 4; j++) {
            qv[j].x *= CSC; qv[j].y *= CSC; qv[j].z *= CSC; qv[j].w *= CSC;
        }
        uint4 H, L;
        SPLIT2(qv[0].x, qv[0].y, H.x, L.x); SPLIT2(qv[0].z, qv[0].w, H.y, L.y);
        SPLIT2(qv[1].x, qv[1].y, H.z, L.z); SPLIT2(qv[1].z, qv[1].w, H.w, L.w);
        *(uint4*)(sm + AT_QH + tid * 48) = H;
        *(uint4*)(sm + AT_QL + tid * 48) = L;
        SPLIT2(qv[2].x, qv[2].y, H.x, L.x); SPLIT2(qv[2].z, qv[2].w, H.y, L.y);
        SPLIT2(qv[3].x, qv[3].y, H.z, L.z); SPLIT2(qv[3].z, qv[3].w, H.w, L.w);
        *(uint4*)(sm + AT_QH + tid * 48 + 16) = H;
        *(uint4*)(sm + AT_QL + tid * 48 + 16) = L;
        SPLIT2(kv[0].x, kv[0].y, H.x, L.x); SPLIT2(kv[0].z, kv[0].w, H.y, L.y);
        SPLIT2(kv[1].x, kv[1].y, H.z, L.z); SPLIT2(kv[1].z, kv[1].w, H.w, L.w);
        *(uint4*)(sm + AT_KH + tid * 48) = H;
        *(uint4*)(sm + AT_KL + tid * 48) = L;
        SPLIT2(kv[2].x, kv[2].y, H.x, L.x); SPLIT2(kv[2].z, kv[2].w, H.y, L.y);
        SPLIT2(kv[3].x, kv[3].y, H.z, L.z); SPLIT2(kv[3].z, kv[3].w, H.w, L.w);
        *(uint4*)(sm + AT_KH + tid * 48 + 16) = H;
        *(uint4*)(sm + AT_KL + tid * 48 + 16) = L;

        float4 vv[4] = {v4[0], v4[1], v4[2], v4[3]};
        #pragma unroll
        for (int j = 0; j < 4; j++) {
            float vals[4] = {vv[j].x, vv[j].y, vv[j].z, vv[j].w};
            #pragma unroll
            for (int e = 0; e < 4; e++) {
                const int d = 4 * j + e;
                const u16 hh = f2bf(vals[e]);
                *(u16*)(sm + AT_VTH + d * 432 + tid * 2) = hh;
                *(u16*)(sm + AT_VTL + d * 432 + tid * 2) = f2bf(vals[e] - bf2f(hh));
            }
        }
    } else if (tid < 208) {   // zero-pad Q/K rows 200..207
        const uint4 z = make_uint4(0, 0, 0, 0);
        #pragma unroll
        for (int a = 0; a < 2; a++) {
            *(uint4*)(sm + AT_QH + tid * 48 + a * 16) = z;
            *(uint4*)(sm + AT_QL + tid * 48 + a * 16) = z;
            *(uint4*)(sm + AT_KH + tid * 48 + a * 16) = z;
            *(uint4*)(sm + AT_KL + tid * 48 + a * 16) = z;
        }
    }
    for (int i = tid; i < 256; i += 224) {   // zero-pad Vt cols 200..215
        const int d = i >> 4, c = 200 + (i & 15);
        *(u16*)(sm + AT_VTH + d * 432 + c * 2) = 0;
        *(u16*)(sm + AT_VTL + d * 432 + c * 2) = 0;
    }
    __syncthreads();

    const int lane = tid & 31;
    const int w    = tid >> 5;
    const int grp  = lane >> 3;
    const int qd   = lane & 3;
    const int mt0 = 2 * w, mt1 = 2 * w + 1;
    const bool do1 = (mt1 * 16) < TT;   // tile 13 is pure pad

    const u32 arow = (u32)(((grp & 1) * 8 + (lane & 7)) * 48 + (grp >> 1) * 16);
    u32 Ah0[4], Al0[4], Ah1[4] = {0,0,0,0}, Al1[4] = {0,0,0,0};
    {
        const u32 a0 = sb + AT_QH + (u32)(mt0 * 16) * 48 + arow;
        ldmx4(Ah0[0], Ah0[1], Ah0[2], Ah0[3], a0);
        ldmx4(Al0[0], Al0[1], Al0[2], Al0[3], a0 + (AT_QL - AT_QH));
        if (do1) {
            ldmx4(Ah1[0], Ah1[1], Ah1[2], Ah1[3], a0 + 768);
            ldmx4(Al1[0], Al1[1], Al1[2], Al1[3], a0 + 768 + (AT_QL - AT_QH));
        }
    }
    const u32 kaddr = sb + AT_KH + (u32)((((grp >> 1) * 8) + (lane & 7)) * 48 + (grp & 1) * 16);
    const u32 vaddr = sb + AT_VTH + (u32)((((grp >> 1) * 8) + (lane & 7)) * 432 + (grp & 1) * 16);

    float o00[4] = {0,0,0,0}, o01[4] = {0,0,0,0};
    float o10[4] = {0,0,0,0}, o11[4] = {0,0,0,0};
    ull lA0 = 0, lB0 = 0, lA1 = 0, lB1 = 0;

    for (int np = 0; np < kcnt; np++) {
        u32 KBh[4], KBl[4], Vbh[4], Vbl[4];
        const u32 ko = kaddr + (u32)(np * 768);
        ldmx4(KBh[0], KBh[1], KBh[2], KBh[3], ko);
        ldmx4(KBl[0], KBl[1], KBl[2], KBl[3], ko + (AT_KL - AT_KH));
        const u32 vo = vaddr + (u32)(np * 32);
        ldmx4(Vbh[0], Vbh[1], Vbh[2], Vbh[3], vo);
        ldmx4(Vbl[0], Vbl[1], Vbl[2], Vbl[3], vo + (AT_VTL - AT_VTH));

        const int c0 = np * 16 + 2 * qd;
        const ull m0 = pack2(c0 < len ? 1.f : 0.f, (c0 + 1) < len ? 1.f : 0.f);
        const ull m1 = pack2((c0 + 8) < len ? 1.f : 0.f, (c0 + 9) < len ? 1.f : 0.f);

        {   // m-tile 0
            u32 aE[4];
            #pragma unroll
            for (int sub = 0; sub < 2; sub++) {
                float s[4] = {0.f, 0.f, 0.f, 0.f};
                mma16816(s, Ah0, KBh[sub * 2], KBh[sub * 2 + 1]);
                mma16816(s, Ah0, KBl[sub * 2], KBl[sub * 2 + 1]);
                mma16816(s, Al0, KBh[sub * 2], KBh[sub * 2 + 1]);
                const ull m = sub ? m1 : m0;
                const ull eA = fmul2(exp2p(pack2(s[0], s[1])), m);
                const ull eB = fmul2(exp2p(pack2(s[2], s[3])), m);
                lA0 = fadd2(lA0, eA);
                lB0 = fadd2(lB0, eB);
                aE[sub * 2]     = cvt_bf16x2p(eA);
                aE[sub * 2 + 1] = cvt_bf16x2p(eB);
            }
            mma16816(o00, aE, Vbh[0], Vbh[1]);
            mma16816(o00, aE, Vbl[0], Vbl[1]);
            mma16816(o01, aE, Vbh[2], Vbh[3]);
            mma16816(o01, aE, Vbl[2], Vbl[3]);
        }
        if (do1) {   // m-tile 1
            u32 aE[4];
            #pragma unroll
            for (int sub = 0; sub < 2; sub++) {
                float s[4] = {0.f, 0.f, 0.f, 0.f};
                mma16816(s, Ah1, KBh[sub * 2], KBh[sub * 2 + 1]);
                mma16816(s, Ah1, KBl[sub * 2], KBl[sub * 2 + 1]);
                mma16816(s, Al1, KBh[sub * 2], KBh[sub * 2 + 1]);
                const ull m = sub ? m1 : m0;
                const ull eA = fmul2(exp2p(pack2(s[0], s[1])), m);
                const ull eB = fmul2(exp2p(pack2(s[2], s[3])), m);
                lA1 = fadd2(lA1, eA);
                lB1 = fadd2(lB1, eB);
                aE[sub * 2]     = cvt_bf16x2p(eA);
                aE[sub * 2 + 1] = cvt_bf16x2p(eB);
            }
            mma16816(o10, aE, Vbh[0], Vbh[1]);
            mma16816(o10, aE, Vbl[0], Vbl[1]);
            mma16816(o11, aE, Vbh[2], Vbh[3]);
            mma16816(o11, aE, Vbl[2], Vbl[3]);
        }
    }

    float* po = out + (size_t)b * TT * UU + h * DH;
    attn_store(po, mt0, lane, o00, o01, lA0, lB0);
    if (do1) attn_store(po, mt1, lane, o10, o11, lA1, lB1);
}

// ---------------------------------------------------------------------------
// Kernel 3: proj + residual + in-register LN (unchanged, proven)
// ---------------------------------------------------------------------------
#define PJ_AH 0
#define PJ_AL 18432
#define PJ_W  36864
#define PJ_SMEM (36864 + 18432)

__global__ __launch_bounds__(256, 3)
void proj_mma(const float* __restrict__ A, const float* __restrict__ X,
              const float* __restrict__ gamma, const float* __restrict__ beta,
              float* __restrict__ out)
{
    extern __shared__ char sm[];
    const u32 sb = smem_u32(sm);
    const int tid = threadIdx.x;
    const size_t row0 = (size_t)blockIdx.x * 128;

    {
        const char* src = (const char*)g_wo;
        for (int i = tid; i < 1152; i += 256)
            cp_async16(sb + PJ_W + i * 16, src + i * 16);
        asm volatile("cp.async.commit_group;");
    }
    {
        const float4* as = (const float4*)(A + row0 * UU);
        for (int i = tid; i < 2048; i += 256) {
            float4 v = as[i];
            const int r = i >> 4, k = (i & 15) * 4;
            u16 h0 = f2bf(v.x), h1 = f2bf(v.y), h2 = f2bf(v.z), h3 = f2bf(v.w);
            ushort4 H; H.x = h0; H.y = h1; H.z = h2; H.w = h3;
            ushort4 L;
            L.x = f2bf(v.x - bf2f(h0)); L.y = f2bf(v.y - bf2f(h1));
            L.z = f2bf(v.z - bf2f(h2)); L.w = f2bf(v.w - bf2f(h3));
            *(ushort4*)(sm + PJ_AH + (r * 72 + k) * 2) = H;
            *(ushort4*)(sm + PJ_AL + (r * 72 + k) * 2) = L;
        }
    }
    asm volatile("cp.async.wait_group 0;");
    __syncthreads();

    const int lane = tid & 31;
    const int wid  = tid >> 5;
    const int rg = wid * 16;
    const int grp = lane >> 3;
    const u32 a_base = sb + PJ_AH +
        (u32)((rg + (grp & 1) * 8 + (lane & 7)) * 144 + (grp >> 1) * 16);
    const u32 b_base = sb + PJ_W +
        (u32)(((grp >> 1) * 8 + (lane & 7)) * 144 + (grp & 1) * 16);
    const u32 ALOFF = 18432, WLOFF = 9216;

    float acc[8][4];
    #pragma unroll
    for (int j = 0; j < 8; j++)
        #pragma unroll
        for (int q = 0; q < 4; q++) acc[j][q] = 0.f;

    #pragma unroll
    for (int ks = 0; ks < 4; ks++) {
        const u32 kb = (u32)(ks * 32);
        u32 Ah[4], Al[4];
        ldmx4(Ah[0], Ah[1], Ah[2], Ah[3], a_base + kb);
        ldmx4(Al[0], Al[1], Al[2], Al[3], a_base + ALOFF + kb);
        #pragma unroll
        for (int jp = 0; jp < 4; jp++) {
            u32 Bh[4], Bl[4];
            const u32 bo = b_base + (u32)(jp * 2304) + kb;
            ldmx4(Bh[0], Bh[1], Bh[2], Bh[3], bo);
            ldmx4(Bl[0], Bl[1], Bl[2], Bl[3], bo + WLOFF);
            #pragma unroll
            for (int js = 0; js < 2; js++) {
                float* a = acc[jp * 2 + js];
                mma16816(a, Ah, Bh[js * 2], Bh[js * 2 + 1]);
                mma16816(a, Ah, Bl[js * 2], Bl[js * 2 + 1]);
                mma16816(a, Al, Bh[js * 2], Bh[js * 2 + 1]);
            }
        }
    }

    const size_t rowA = row0 + rg + (lane >> 2);
    const size_t rowB = rowA + 8;
    const int cq = 2 * (lane & 3);

    #pragma unroll
    for (int j = 0; j < 8; j++) {
        const int c = 8 * j + cq;
        float2 xa = *(const float2*)(X + rowA * UU + c);
        float2 xb = *(const float2*)(X + rowB * UU + c);
        acc[j][0] += xa.x; acc[j][1] += xa.y;
        acc[j][2] += xb.x; acc[j][3] += xb.y;
    }

    float sA = 0.f, sB = 0.f;
    #pragma unroll
    for (int j = 0; j < 8; j++) {
        sA += acc[j][0] + acc[j][1];
        sB += acc[j][2] + acc[j][3];
    }
    sA += __shfl_xor_sync(0xFFFFFFFFu, sA, 1);
    sA += __shfl_xor_sync(0xFFFFFFFFu, sA, 2);
    sB += __shfl_xor_sync(0xFFFFFFFFu, sB, 1);
    sB += __shfl_xor_sync(0xFFFFFFFFu, sB, 2);
    const float mA = sA * (1.0f / 64.0f);
    const float mB = sB * (1.0f / 64.0f);

    float vA = 0.f, vB = 0.f;
    #pragma unroll
    for (int j = 0; j < 8; j++) {
        float d0 = acc[j][0] - mA, d1 = acc[j][1] - mA;
        float d2 = acc[j][2] - mB, d3 = acc[j][3] - mB;
        vA = fmaf(d0, d0, fmaf(d1, d1, vA));
        vB = fmaf(d2, d2, fmaf(d3, d3, vB));
    }
    vA += __shfl_xor_sync(0xFFFFFFFFu, vA, 1);
    vA += __shfl_xor_sync(0xFFFFFFFFu, vA, 2);
    vB += __shfl_xor_sync(0xFFFFFFFFu, vB, 1);
    vB += __shfl_xor_sync(0xFFFFFFFFu, vB, 2);
    const float iA = rsqrtf(vA * (1.0f / 64.0f) + 1e-9f);
    const float iB = rsqrtf(vB * (1.0f / 64.0f) + 1e-9f);

    #pragma unroll
    for (int j = 0; j < 8; j++) {
        const int c = 8 * j + cq;
        const float2 gg = *(const float2*)(gamma + c);
        const float2 bb = *(const float2*)(beta + c);
        float2 oa, ob;
        oa.x = fmaf((acc[j][0] - mA) * iA, gg.x, bb.x);
        oa.y = fmaf((acc[j][1] - mA) * iA, gg.y, bb.y);
        ob.x = fmaf((acc[j][2] - mB) * iB, gg.x, bb.x);
        ob.y = fmaf((acc[j][3] - mB) * iB, gg.y, bb.y);
        *(float2*)(out + rowA * UU + c) = oa;
        *(float2*)(out + rowB * UU + c) = ob;
    }
}

// ---------------------------------------------------------------------------
extern "C" void kernel_launch(void* const* d_in, const int* in_sizes, int n_in,
                              void* d_out, int out_size)
{
    const float* input_info = (const float*)d_in[0];
    const int*   keys_len   = (const int*)d_in[1];
    const float* W          = (const float*)d_in[2];
    const float* W_output   = (const float*)d_in[3];
    const float* gamma      = (const float*)d_in[4];
    const float* beta       = (const float*)d_in[5];
    float* out = (float*)d_out;

    float* qkv;  cudaGetSymbolAddress((void**)&qkv,  g_qkv);
    float* attn; cudaGetSymbolAddress((void**)&attn, g_attn);

    cudaFuncSetAttribute(qkv_mma,  cudaFuncAttributeMaxDynamicSharedMemorySize, QK_SMEM);
    cudaFuncSetAttribute(attn_mma, cudaFuncAttributeMaxDynamicSharedMemorySize, AT_SMEM);
    cudaFuncSetAttribute(proj_mma, cudaFuncAttributeMaxDynamicSharedMemorySize, PJ_SMEM);

    prep_weights<<<64, 256>>>(W, W_output);

    qkv_mma<<<(BB * TT) / 64, 256, QK_SMEM>>>(input_info, qkv);

    dim3 g2(BB, HH);
    attn_mma<<<g2, 224, AT_SMEM>>>(qkv, keys_len, attn);

    proj_mma<<<(BB * TT) / 128, 256, PJ_SMEM>>>(attn, input_info, gamma, beta, out);
}

// round 9
// speedup vs baseline: 2.2485x; 1.4852x over previous
#include <cuda_runtime.h>
#include <math.h>

#define BB 1024
#define TT 200
#define EE 64
#define UU 64
#define HH 4
#define DH 16
#define C3U 192

typedef unsigned long long ull;
typedef unsigned int u32;
typedef unsigned short u16;

// bf16 intermediates (traffic halved vs fp32)
__device__ __align__(16) u16 g_qkv16[(size_t)BB * TT * C3U];  // Q pre-scaled by CSC
__device__ __align__(16) u16 g_attn16[(size_t)BB * TT * UU];
__device__ __align__(16) u16 g_wq[192 * 72];   // W^T bf16, rows padded to 72
__device__ __align__(16) u16 g_wo[64 * 72];    // Wo^T bf16

// ---------------------------------------------------------------------------
__device__ __forceinline__ u16 f2bf(float f) {
    u32 u = __float_as_uint(f);
    u32 r = u + 0x7FFFu + ((u >> 16) & 1u);
    return (u16)(r >> 16);
}
__device__ __forceinline__ u32 bfx2(float lo, float hi) {
    u32 r; asm("cvt.rn.bf16x2.f32 %0, %1, %2;" : "=r"(r) : "f"(hi), "f"(lo));
    return r;
}
__device__ __forceinline__ ull pack2(float x, float y) {
    ull r; asm("mov.b64 %0, {%1, %2};" : "=l"(r) : "f"(x), "f"(y)); return r;
}
__device__ __forceinline__ void unpack2(ull v, float& x, float& y) {
    asm("mov.b64 {%0, %1}, %2;" : "=f"(x), "=f"(y) : "l"(v));
}
__device__ __forceinline__ ull ffma2(ull a, ull b, ull c) {
    ull d; asm("fma.rn.f32x2 %0, %1, %2, %3;" : "=l"(d) : "l"(a), "l"(b), "l"(c)); return d;
}
__device__ __forceinline__ ull fmul2(ull a, ull b) {
    ull d; asm("mul.rn.f32x2 %0, %1, %2;" : "=l"(d) : "l"(a), "l"(b)); return d;
}
__device__ __forceinline__ ull fadd2(ull a, ull b) {
    ull d; asm("add.rn.f32x2 %0, %1, %2;" : "=l"(d) : "l"(a), "l"(b)); return d;
}

// packed 2^y (y already log2-scaled)
__device__ __forceinline__ ull exp2p(ull y2) {
    const float BIG = 12582912.0f;
    ull t2  = fadd2(y2, pack2(BIG, BIG));
    ull nf2 = fadd2(t2, pack2(-BIG, -BIG));
    ull r2  = ffma2(nf2, pack2(-1.f, -1.f), y2);
    ull p2  = ffma2(pack2(0.00133335581f, 0.00133335581f), r2,
                    pack2(0.00961812911f, 0.00961812911f));
    p2 = ffma2(p2, r2, pack2(0.0555041087f, 0.0555041087f));
    p2 = ffma2(p2, r2, pack2(0.240226507f, 0.240226507f));
    p2 = ffma2(p2, r2, pack2(0.693147182f, 0.693147182f));
    p2 = ffma2(p2, r2, pack2(1.f, 1.f));
    float pa, pb, ta, tb;
    unpack2(p2, pa, pb);
    unpack2(t2, ta, tb);
    const float e0 = __int_as_float(__float_as_int(pa) + (__float_as_int(ta) << 23));
    const float e1 = __int_as_float(__float_as_int(pb) + (__float_as_int(tb) << 23));
    return pack2(e0, e1);
}
__device__ __forceinline__ u32 cvt_bf16x2p(ull e2) {
    float x, y; unpack2(e2, x, y);
    return bfx2(x, y);
}

// ---------------------------------------------------------------------------
__device__ __forceinline__ u32 smem_u32(const void* p) {
    u32 a; asm("{ .reg .u64 t; cvta.to.shared.u64 t, %1; cvt.u32.u64 %0, t; }"
               : "=r"(a) : "l"(p));
    return a;
}
__device__ __forceinline__ void ldmx4(u32& r0, u32& r1, u32& r2, u32& r3, u32 a) {
    asm volatile("ldmatrix.sync.aligned.m8n8.x4.shared.b16 {%0,%1,%2,%3}, [%4];"
                 : "=r"(r0), "=r"(r1), "=r"(r2), "=r"(r3) : "r"(a));
}
__device__ __forceinline__ void ldmx4t(u32& r0, u32& r1, u32& r2, u32& r3, u32 a) {
    asm volatile("ldmatrix.sync.aligned.m8n8.x4.trans.shared.b16 {%0,%1,%2,%3}, [%4];"
                 : "=r"(r0), "=r"(r1), "=r"(r2), "=r"(r3) : "r"(a));
}
__device__ __forceinline__ void mma16816(float* c, const u32* a, u32 b0, u32 b1) {
    asm volatile(
        "mma.sync.aligned.m16n8k16.row.col.f32.bf16.bf16.f32 "
        "{%0,%1,%2,%3}, {%4,%5,%6,%7}, {%8,%9}, {%0,%1,%2,%3};"
        : "+f"(c[0]), "+f"(c[1]), "+f"(c[2]), "+f"(c[3])
        : "r"(a[0]), "r"(a[1]), "r"(a[2]), "r"(a[3]), "r"(b0), "r"(b1));
}
__device__ __forceinline__ void cp_async16(u32 dst, const void* src) {
    asm volatile("cp.async.cg.shared.global [%0], [%1], 16;" :: "r"(dst), "l"(src));
}

// ---------------------------------------------------------------------------
// Kernel 0: transpose + bf16 round of W and Wo (B operands, n-major).
// ---------------------------------------------------------------------------
__global__ void prep_weights(const float* __restrict__ W, const float* __restrict__ Wo)
{
    const int i = blockIdx.x * 256 + threadIdx.x;   // 0..16383
    if (i < 12288) {
        const int k = i / 192, n = i % 192;
        g_wq[n * 72 + k] = f2bf(W[i]);
    } else {
        const int j = i - 12288;
        const int k = j / 64, n = j % 64;
        g_wo[n * 72 + k] = f2bf(Wo[j]);
    }
}

// ---------------------------------------------------------------------------
// Kernel 1: QKV = X @ W, single bf16 MMA, bf16 output, Q cols pre-scaled.
// CTA: 64 rows x 192 cols, 8 warps (warp = 32 x 48).
// ---------------------------------------------------------------------------
#define QK_X 0
#define QK_W 9216
#define QK_SMEM (9216 + 27648)   // 36864

__global__ __launch_bounds__(256, 3)
void qkv_mma(const float* __restrict__ X, u16* __restrict__ out16)
{
    extern __shared__ char sm[];
    const u32 sb = smem_u32(sm);
    const int tid = threadIdx.x;
    const size_t row0 = (size_t)blockIdx.x * 64;

    {   // async-stage W (27648B)
        const char* src = (const char*)g_wq;
        for (int i = tid; i < 1728; i += 256)
            cp_async16(sb + QK_W + i * 16, src + i * 16);
        asm volatile("cp.async.commit_group;");
    }
    {   // stage X as bf16 [64][72]
        const float4* xs = (const float4*)(X + row0 * EE);
        for (int i = tid; i < 1024; i += 256) {
            float4 v = xs[i];
            const int r = i >> 4, k = (i & 15) * 4;
            uint2 p;
            p.x = bfx2(v.x, v.y);
            p.y = bfx2(v.z, v.w);
            *(uint2*)(sm + QK_X + (r * 72 + k) * 2) = p;
        }
    }
    asm volatile("cp.async.wait_group 0;");
    __syncthreads();

    const int lane = tid & 31;
    const int wid  = tid >> 5;
    const int rg = (wid & 1) * 32;
    const int cg = (wid >> 1) * 48;
    const int grp = lane >> 3;
    const u32 a_base = sb + QK_X +
        (u32)((rg + (grp & 1) * 8 + (lane & 7)) * 144 + (grp >> 1) * 16);
    const u32 b_base = sb + QK_W +
        (u32)((cg + (grp >> 1) * 8 + (lane & 7)) * 144 + (grp & 1) * 16);

    float acc[2][6][4];
    #pragma unroll
    for (int m = 0; m < 2; m++)
        #pragma unroll
        for (int j = 0; j < 6; j++)
            #pragma unroll
            for (int q = 0; q < 4; q++) acc[m][j][q] = 0.f;

    #pragma unroll
    for (int ks = 0; ks < 4; ks++) {
        const u32 kb = (u32)(ks * 32);
        u32 A0[4], A1[4];
        ldmx4(A0[0], A0[1], A0[2], A0[3], a_base + kb);
        ldmx4(A1[0], A1[1], A1[2], A1[3], a_base + 2304 + kb);
        #pragma unroll
        for (int jp = 0; jp < 3; jp++) {
            u32 Bh[4];
            ldmx4(Bh[0], Bh[1], Bh[2], Bh[3], b_base + (u32)(jp * 2304) + kb);
            #pragma unroll
            for (int js = 0; js < 2; js++) {
                mma16816(acc[0][jp * 2 + js], A0, Bh[js * 2], Bh[js * 2 + 1]);
                mma16816(acc[1][jp * 2 + js], A1, Bh[js * 2], Bh[js * 2 + 1]);
            }
        }
    }

    const float CSC = 0.36067376022224085f;   // 0.25*log2(e), folded into Q
    #pragma unroll
    for (int m = 0; m < 2; m++) {
        const size_t r = row0 + rg + m * 16 + (lane >> 2);
        #pragma unroll
        for (int j = 0; j < 6; j++) {
            const int c = cg + 8 * j + 2 * (lane & 3);
            const float sc = (c < UU) ? CSC : 1.0f;
            *(u32*)(out16 + r * C3U + c) =
                bfx2(acc[m][j][0] * sc, acc[m][j][1] * sc);
            *(u32*)(out16 + (r + 8) * C3U + c) =
                bfx2(acc[m][j][2] * sc, acc[m][j][3] * sc);
        }
    }
}

// ---------------------------------------------------------------------------
// Kernel 2: FA2 HMMA attention, single-bf16 operands, V via ldmatrix.trans.
// One CTA per (b,h), 7 warps x 2 m-tiles of 16 queries.
// smem: Q [208][24]bf16 | K [208][24] | V [208][24]  (48B rows, conflict-free)
// ---------------------------------------------------------------------------
#define AT_Q 0
#define AT_K 9984
#define AT_V 19968
#define AT_SMEM 29952

__device__ __forceinline__ void attn_store16(u16* po, int mt, int lane,
                                             const float* oA, const float* oB,
                                             ull lA, ull lB)
{
    float x, y;
    unpack2(lA, x, y); float la = x + y;
    la += __shfl_xor_sync(0xFFFFFFFFu, la, 1);
    la += __shfl_xor_sync(0xFFFFFFFFu, la, 2);
    unpack2(lB, x, y); float lb = x + y;
    lb += __shfl_xor_sync(0xFFFFFFFFu, lb, 1);
    lb += __shfl_xor_sync(0xFFFFFFFFu, lb, 2);
    const float iA = 1.f / la, iB = 1.f / lb;
    const int cb = 2 * (lane & 3);
    const int rA = mt * 16 + (lane >> 2), rB = rA + 8;
    if (rA < TT) {
        *(u32*)(po + (size_t)rA * UU + cb)     = bfx2(oA[0] * iA, oA[1] * iA);
        *(u32*)(po + (size_t)rA * UU + 8 + cb) = bfx2(oB[0] * iA, oB[1] * iA);
    }
    if (rB < TT) {
        *(u32*)(po + (size_t)rB * UU + cb)     = bfx2(oA[2] * iB, oA[3] * iB);
        *(u32*)(po + (size_t)rB * UU + 8 + cb) = bfx2(oB[2] * iB, oB[3] * iB);
    }
}

__global__ __launch_bounds__(224, 3)
void attn_mma(const u16* __restrict__ qkv16, const int* __restrict__ lens,
              u16* __restrict__ out16)
{
    extern __shared__ char sm[];
    const u32 sb = smem_u32(sm);
    const int tid = threadIdx.x;
    const int b = blockIdx.x, h = blockIdx.y;

    int len = lens[b];
    if (len < 1) len = 1;
    if (len > TT) len = TT;
    const int kcnt = (len + 15) >> 4;

    // stage: pure copy (Q already scaled, all bf16)
    if (tid < TT) {
        const u16* row = qkv16 + ((size_t)b * TT + tid) * C3U + h * DH;
        uint4 q0 = *(const uint4*)(row);
        uint4 q1 = *(const uint4*)(row + 8);
        uint4 k0 = *(const uint4*)(row + UU);
        uint4 k1 = *(const uint4*)(row + UU + 8);
        uint4 v0 = *(const uint4*)(row + 2 * UU);
        uint4 v1 = *(const uint4*)(row + 2 * UU + 8);
        *(uint4*)(sm + AT_Q + tid * 48)      = q0;
        *(uint4*)(sm + AT_Q + tid * 48 + 16) = q1;
        *(uint4*)(sm + AT_K + tid * 48)      = k0;
        *(uint4*)(sm + AT_K + tid * 48 + 16) = k1;
        *(uint4*)(sm + AT_V + tid * 48)      = v0;
        *(uint4*)(sm + AT_V + tid * 48 + 16) = v1;
    } else if (tid < 208) {
        const uint4 z = make_uint4(0, 0, 0, 0);
        *(uint4*)(sm + AT_Q + tid * 48)      = z;
        *(uint4*)(sm + AT_Q + tid * 48 + 16) = z;
        *(uint4*)(sm + AT_K + tid * 48)      = z;
        *(uint4*)(sm + AT_K + tid * 48 + 16) = z;
        *(uint4*)(sm + AT_V + tid * 48)      = z;
        *(uint4*)(sm + AT_V + tid * 48 + 16) = z;
    }
    __syncthreads();

    const int lane = tid & 31;
    const int w    = tid >> 5;
    const int grp  = lane >> 3;
    const int qd   = lane & 3;
    const int mt0 = 2 * w, mt1 = 2 * w + 1;
    const bool do1 = (mt1 * 16) < TT;

    const u32 arow = (u32)(((grp & 1) * 8 + (lane & 7)) * 48 + (grp >> 1) * 16);
    u32 A0[4], A1[4] = {0, 0, 0, 0};
    {
        const u32 a0 = sb + AT_Q + (u32)(mt0 * 16) * 48 + arow;
        ldmx4(A0[0], A0[1], A0[2], A0[3], a0);
        if (do1) ldmx4(A1[0], A1[1], A1[2], A1[3], a0 + 768);
    }
    const u32 kaddr = sb + AT_K + (u32)((((grp >> 1) * 8) + (lane & 7)) * 48 + (grp & 1) * 16);
    // V trans: rows = keys, cols = d; tiles (k0-7,d0-7)(k8-15,d0-7)(k0-7,d8-15)(k8-15,d8-15)
    const u32 vaddr = sb + AT_V + (u32)((((grp & 1) * 8) + (lane & 7)) * 48 + (grp >> 1) * 16);

    float o00[4] = {0,0,0,0}, o01[4] = {0,0,0,0};
    float o10[4] = {0,0,0,0}, o11[4] = {0,0,0,0};
    ull lA0 = 0, lB0 = 0, lA1 = 0, lB1 = 0;

    for (int np = 0; np < kcnt; np++) {
        u32 KB[4], VB[4];
        ldmx4(KB[0], KB[1], KB[2], KB[3], kaddr + (u32)(np * 768));
        ldmx4t(VB[0], VB[1], VB[2], VB[3], vaddr + (u32)(np * 768));

        const int c0 = np * 16 + 2 * qd;
        const ull m0 = pack2(c0 < len ? 1.f : 0.f, (c0 + 1) < len ? 1.f : 0.f);
        const ull m1 = pack2((c0 + 8) < len ? 1.f : 0.f, (c0 + 9) < len ? 1.f : 0.f);

        {   // m-tile 0
            u32 aE[4];
            #pragma unroll
            for (int sub = 0; sub < 2; sub++) {
                float s[4] = {0.f, 0.f, 0.f, 0.f};
                mma16816(s, A0, KB[sub * 2], KB[sub * 2 + 1]);
                const ull m = sub ? m1 : m0;
                const ull eA = fmul2(exp2p(pack2(s[0], s[1])), m);
                const ull eB = fmul2(exp2p(pack2(s[2], s[3])), m);
                lA0 = fadd2(lA0, eA);
                lB0 = fadd2(lB0, eB);
                aE[sub * 2]     = cvt_bf16x2p(eA);
                aE[sub * 2 + 1] = cvt_bf16x2p(eB);
            }
            mma16816(o00, aE, VB[0], VB[1]);
            mma16816(o01, aE, VB[2], VB[3]);
        }
        if (do1) {   // m-tile 1
            u32 aE[4];
            #pragma unroll
            for (int sub = 0; sub < 2; sub++) {
                float s[4] = {0.f, 0.f, 0.f, 0.f};
                mma16816(s, A1, KB[sub * 2], KB[sub * 2 + 1]);
                const ull m = sub ? m1 : m0;
                const ull eA = fmul2(exp2p(pack2(s[0], s[1])), m);
                const ull eB = fmul2(exp2p(pack2(s[2], s[3])), m);
                lA1 = fadd2(lA1, eA);
                lB1 = fadd2(lB1, eB);
                aE[sub * 2]     = cvt_bf16x2p(eA);
                aE[sub * 2 + 1] = cvt_bf16x2p(eB);
            }
            mma16816(o10, aE, VB[0], VB[1]);
            mma16816(o11, aE, VB[2], VB[3]);
        }
    }

    u16* po = out16 + (size_t)b * TT * UU + h * DH;
    attn_store16(po, mt0, lane, o00, o01, lA0, lB0);
    if (do1) attn_store16(po, mt1, lane, o10, o11, lA1, lB1);
}

// ---------------------------------------------------------------------------
// Kernel 3: Y = A @ Wo + X; in-register LN. A bf16 single, Wo bf16 single.
// CTA: 128 rows, 8 warps (16 rows x 64 cols each).
// ---------------------------------------------------------------------------
#define PJ_A 0
#define PJ_W 18432
#define PJ_SMEM (18432 + 9216)   // 27648

__global__ __launch_bounds__(256, 3)
void proj_mma(const u16* __restrict__ A16, const float* __restrict__ X,
              const float* __restrict__ gamma, const float* __restrict__ beta,
              float* __restrict__ out)
{
    extern __shared__ char sm[];
    const u32 sb = smem_u32(sm);
    const int tid = threadIdx.x;
    const size_t row0 = (size_t)blockIdx.x * 128;

    {   // async-stage Wo (9216B)
        const char* src = (const char*)g_wo;
        for (int i = tid; i < 576; i += 256)
            cp_async16(sb + PJ_W + i * 16, src + i * 16);
        asm volatile("cp.async.commit_group;");
    }
    {   // stage A [128][72] bf16 (copy)
        const uint4* as = (const uint4*)(A16 + row0 * UU);
        for (int i = tid; i < 1024; i += 256) {
            const int r = i >> 3, q = i & 7;
            *(uint4*)(sm + PJ_A + r * 144 + q * 16) = as[i];
        }
    }
    asm volatile("cp.async.wait_group 0;");
    __syncthreads();

    const int lane = tid & 31;
    const int wid  = tid >> 5;
    const int rg = wid * 16;
    const int grp = lane >> 3;
    const u32 a_base = sb + PJ_A +
        (u32)((rg + (grp & 1) * 8 + (lane & 7)) * 144 + (grp >> 1) * 16);
    const u32 b_base = sb + PJ_W +
        (u32)(((grp >> 1) * 8 + (lane & 7)) * 144 + (grp & 1) * 16);

    float acc[8][4];
    #pragma unroll
    for (int j = 0; j < 8; j++)
        #pragma unroll
        for (int q = 0; q < 4; q++) acc[j][q] = 0.f;

    #pragma unroll
    for (int ks = 0; ks < 4; ks++) {
        const u32 kb = (u32)(ks * 32);
        u32 Af[4];
        ldmx4(Af[0], Af[1], Af[2], Af[3], a_base + kb);
        #pragma unroll
        for (int jp = 0; jp < 4; jp++) {
            u32 Bh[4];
            ldmx4(Bh[0], Bh[1], Bh[2], Bh[3], b_base + (u32)(jp * 2304) + kb);
            mma16816(acc[jp * 2],     Af, Bh[0], Bh[1]);
            mma16816(acc[jp * 2 + 1], Af, Bh[2], Bh[3]);
        }
    }

    const size_t rowA = row0 + rg + (lane >> 2);
    const size_t rowB = rowA + 8;
    const int cq = 2 * (lane & 3);

    #pragma unroll
    for (int j = 0; j < 8; j++) {
        const int c = 8 * j + cq;
        float2 xa = *(const float2*)(X + rowA * UU + c);
        float2 xb = *(const float2*)(X + rowB * UU + c);
        acc[j][0] += xa.x; acc[j][1] += xa.y;
        acc[j][2] += xb.x; acc[j][3] += xb.y;
    }

    float sA = 0.f, sB = 0.f;
    #pragma unroll
    for (int j = 0; j < 8; j++) {
        sA += acc[j][0] + acc[j][1];
        sB += acc[j][2] + acc[j][3];
    }
    sA += __shfl_xor_sync(0xFFFFFFFFu, sA, 1);
    sA += __shfl_xor_sync(0xFFFFFFFFu, sA, 2);
    sB += __shfl_xor_sync(0xFFFFFFFFu, sB, 1);
    sB += __shfl_xor_sync(0xFFFFFFFFu, sB, 2);
    const float mA = sA * (1.0f / 64.0f);
    const float mB = sB * (1.0f / 64.0f);

    float vA = 0.f, vB = 0.f;
    #pragma unroll
    for (int j = 0; j < 8; j++) {
        float d0 = acc[j][0] - mA, d1 = acc[j][1] - mA;
        float d2 = acc[j][2] - mB, d3 = acc[j][3] - mB;
        vA = fmaf(d0, d0, fmaf(d1, d1, vA));
        vB = fmaf(d2, d2, fmaf(d3, d3, vB));
    }
    vA += __shfl_xor_sync(0xFFFFFFFFu, vA, 1);
    vA += __shfl_xor_sync(0xFFFFFFFFu, vA, 2);
    vB += __shfl_xor_sync(0xFFFFFFFFu, vB, 1);
    vB += __shfl_xor_sync(0xFFFFFFFFu, vB, 2);
    const float iA = rsqrtf(vA * (1.0f / 64.0f) + 1e-9f);
    const float iB = rsqrtf(vB * (1.0f / 64.0f) + 1e-9f);

    #pragma unroll
    for (int j = 0; j < 8; j++) {
        const int c = 8 * j + cq;
        const float2 gg = *(const float2*)(gamma + c);
        const float2 bb = *(const float2*)(beta + c);
        float2 oa, ob;
        oa.x = fmaf((acc[j][0] - mA) * iA, gg.x, bb.x);
        oa.y = fmaf((acc[j][1] - mA) * iA, gg.y, bb.y);
        ob.x = fmaf((acc[j][2] - mB) * iB, gg.x, bb.x);
        ob.y = fmaf((acc[j][3] - mB) * iB, gg.y, bb.y);
        *(float2*)(out + rowA * UU + c) = oa;
        *(float2*)(out + rowB * UU + c) = ob;
    }
}

// ---------------------------------------------------------------------------
extern "C" void kernel_launch(void* const* d_in, const int* in_sizes, int n_in,
                              void* d_out, int out_size)
{
    const float* input_info = (const float*)d_in[0];
    const int*   keys_len   = (const int*)d_in[1];
    const float* W          = (const float*)d_in[2];
    const float* W_output   = (const float*)d_in[3];
    const float* gamma      = (const float*)d_in[4];
    const float* beta       = (const float*)d_in[5];
    float* out = (float*)d_out;

    u16* qkv16;  cudaGetSymbolAddress((void**)&qkv16,  g_qkv16);
    u16* attn16; cudaGetSymbolAddress((void**)&attn16, g_attn16);

    cudaFuncSetAttribute(qkv_mma,  cudaFuncAttributeMaxDynamicSharedMemorySize, QK_SMEM);
    cudaFuncSetAttribute(attn_mma, cudaFuncAttributeMaxDynamicSharedMemorySize, AT_SMEM);
    cudaFuncSetAttribute(proj_mma, cudaFuncAttributeMaxDynamicSharedMemorySize, PJ_SMEM);

    prep_weights<<<64, 256>>>(W, W_output);

    qkv_mma<<<(BB * TT) / 64, 256, QK_SMEM>>>(input_info, qkv16);

    dim3 g2(BB, HH);
    attn_mma<<<g2, 224, AT_SMEM>>>(qkv16, keys_len, attn16);

    proj_mma<<<(BB * TT) / 128, 256, PJ_SMEM>>>(attn16, input_info, gamma, beta, out);
}

// round 11
// speedup vs baseline: 2.7805x; 1.2366x over previous
#include <cuda_runtime.h>
#include <math.h>

#define BB 1024
#define TT 200
#define EE 64
#define UU 64
#define HH 4
#define DH 16
#define C3U 192

typedef unsigned long long ull;
typedef unsigned int u32;
typedef unsigned short u16;

__device__ __align__(16) u16 g_wq[192 * 72];   // W^T bf16, rows padded to 72
__device__ __align__(16) u16 g_wo[64 * 72];    // Wo^T bf16

// ---------------------------------------------------------------------------
__device__ __forceinline__ u16 f2bf(float f) {
    u32 u = __float_as_uint(f);
    u32 r = u + 0x7FFFu + ((u >> 16) & 1u);
    return (u16)(r >> 16);
}
__device__ __forceinline__ u32 bfx2(float lo, float hi) {
    u32 r; asm("cvt.rn.bf16x2.f32 %0, %1, %2;" : "=r"(r) : "f"(hi), "f"(lo));
    return r;
}
__device__ __forceinline__ ull pack2(float x, float y) {
    ull r; asm("mov.b64 %0, {%1, %2};" : "=l"(r) : "f"(x), "f"(y)); return r;
}
__device__ __forceinline__ void unpack2(ull v, float& x, float& y) {
    asm("mov.b64 {%0, %1}, %2;" : "=f"(x), "=f"(y) : "l"(v));
}
__device__ __forceinline__ ull ffma2(ull a, ull b, ull c) {
    ull d; asm("fma.rn.f32x2 %0, %1, %2, %3;" : "=l"(d) : "l"(a), "l"(b), "l"(c)); return d;
}
__device__ __forceinline__ ull fmul2(ull a, ull b) {
    ull d; asm("mul.rn.f32x2 %0, %1, %2;" : "=l"(d) : "l"(a), "l"(b)); return d;
}
__device__ __forceinline__ ull fadd2(ull a, ull b) {
    ull d; asm("add.rn.f32x2 %0, %1, %2;" : "=l"(d) : "l"(a), "l"(b)); return d;
}

// packed 2^y (y already log2-scaled)
__device__ __forceinline__ ull exp2p(ull y2) {
    const float BIG = 12582912.0f;
    ull t2  = fadd2(y2, pack2(BIG, BIG));
    ull nf2 = fadd2(t2, pack2(-BIG, -BIG));
    ull r2  = ffma2(nf2, pack2(-1.f, -1.f), y2);
    ull p2  = ffma2(pack2(0.00133335581f, 0.00133335581f), r2,
                    pack2(0.00961812911f, 0.00961812911f));
    p2 = ffma2(p2, r2, pack2(0.0555041087f, 0.0555041087f));
    p2 = ffma2(p2, r2, pack2(0.240226507f, 0.240226507f));
    p2 = ffma2(p2, r2, pack2(0.693147182f, 0.693147182f));
    p2 = ffma2(p2, r2, pack2(1.f, 1.f));
    float pa, pb, ta, tb;
    unpack2(p2, pa, pb);
    unpack2(t2, ta, tb);
    const float e0 = __int_as_float(__float_as_int(pa) + (__float_as_int(ta) << 23));
    const float e1 = __int_as_float(__float_as_int(pb) + (__float_as_int(tb) << 23));
    return pack2(e0, e1);
}
__device__ __forceinline__ u32 cvt_bf16x2p(ull e2) {
    float x, y; unpack2(e2, x, y);
    return bfx2(x, y);
}

// ---------------------------------------------------------------------------
__device__ __forceinline__ u32 smem_u32(const void* p) {
    u32 a; asm("{ .reg .u64 t; cvta.to.shared.u64 t, %1; cvt.u32.u64 %0, t; }"
               : "=r"(a) : "l"(p));
    return a;
}
__device__ __forceinline__ void ldmx4(u32& r0, u32& r1, u32& r2, u32& r3, u32 a) {
    asm volatile("ldmatrix.sync.aligned.m8n8.x4.shared.b16 {%0,%1,%2,%3}, [%4];"
                 : "=r"(r0), "=r"(r1), "=r"(r2), "=r"(r3) : "r"(a));
}
__device__ __forceinline__ void ldmx4t(u32& r0, u32& r1, u32& r2, u32& r3, u32 a) {
    asm volatile("ldmatrix.sync.aligned.m8n8.x4.trans.shared.b16 {%0,%1,%2,%3}, [%4];"
                 : "=r"(r0), "=r"(r1), "=r"(r2), "=r"(r3) : "r"(a));
}
__device__ __forceinline__ void mma16816(float* c, const u32* a, u32 b0, u32 b1) {
    asm volatile(
        "mma.sync.aligned.m16n8k16.row.col.f32.bf16.bf16.f32 "
        "{%0,%1,%2,%3}, {%4,%5,%6,%7}, {%8,%9}, {%0,%1,%2,%3};"
        : "+f"(c[0]), "+f"(c[1]), "+f"(c[2]), "+f"(c[3])
        : "r"(a[0]), "r"(a[1]), "r"(a[2]), "r"(a[3]), "r"(b0), "r"(b1));
}
__device__ __forceinline__ void cp_async16(u32 dst, const void* src) {
    asm volatile("cp.async.cg.shared.global [%0], [%1], 16;" :: "r"(dst), "l"(src));
}

// ---------------------------------------------------------------------------
// Kernel 0: transpose + bf16 round of W and Wo (B operands, n-major).
// ---------------------------------------------------------------------------
__global__ void prep_weights(const float* __restrict__ W, const float* __restrict__ Wo)
{
    const int i = blockIdx.x * 256 + threadIdx.x;   // 0..16383
    if (i < 12288) {
        const int k = i / 192, n = i % 192;
        g_wq[n * 72 + k] = f2bf(W[i]);
    } else {
        const int j = i - 12288;
        const int k = j / 64, n = j % 64;
        g_wo[n * 72 + k] = f2bf(Wo[j]);
    }
}

// ---------------------------------------------------------------------------
// Fused kernel: one CTA per batch. 512 threads (16 warps).
// Phase 1: QKV = X@W (bf16 MMA) -> QKV smem (Q pre-scaled by 0.25*log2e)
// Phase 2: FA2 attention from QKV smem -> O bf16 into the retired X buffer
// Phase 3: Y = O@Wo + X (global re-read) ; in-register LN -> out
//
// smem map (bytes):
//   [0,      29952)  X bf16 [208][72] stride 144  -> reused as O after ph.1
//   [29952,  57600)  W^T bf16 [192][72] stride 144
//   [57600,  66816)  Wo^T bf16 [64][72] stride 144
//   [66816, 150016)  QKV bf16 [208][200] stride 400 (Q:0-63 K:64-127 V:128-191)
// ---------------------------------------------------------------------------
#define FU_X   0
#define FU_W   29952
#define FU_WO  57600
#define FU_QKV 66816
#define FU_SMEM 150016

__global__ __launch_bounds__(512, 1)
void fused_mha(const float* __restrict__ X, const int* __restrict__ lens,
               const float* __restrict__ gamma, const float* __restrict__ beta,
               float* __restrict__ out)
{
    extern __shared__ char sm[];
    const u32 sb = smem_u32(sm);
    const int tid = threadIdx.x;
    const int b = blockIdx.x;
    const size_t rowg0 = (size_t)b * TT;

    // ---- staging ----
    {   // cp.async W (27648B = 1728 chunks) + Wo (9216B = 576 chunks)
        const char* srcw = (const char*)g_wq;
        for (int i = tid; i < 1728; i += 512)
            cp_async16(sb + FU_W + i * 16, srcw + i * 16);
        const char* srco = (const char*)g_wo;
        for (int i = tid; i < 576; i += 512)            // FIX: was `if (tid < 576)`
            cp_async16(sb + FU_WO + i * 16, srco + i * 16);
        asm volatile("cp.async.commit_group;");
    }
    {   // X fp32 -> bf16 [208][72]
        const float4* xs = (const float4*)(X + rowg0 * EE);
        for (int i = tid; i < 3200; i += 512) {
            float4 v = xs[i];
            const int r = i >> 4, q = i & 15;
            uint2 p;
            p.x = bfx2(v.x, v.y);
            p.y = bfx2(v.z, v.w);
            *(uint2*)(sm + FU_X + r * 144 + q * 8) = p;
        }
        if (tid < 72)   // zero pad rows 200..207
            *(uint4*)(sm + FU_X + 200 * 144 + tid * 16) = make_uint4(0, 0, 0, 0);
    }
    asm volatile("cp.async.wait_group 0;");
    __syncthreads();

    const int lane = tid & 31;
    const int w    = tid >> 5;      // 0..15
    const int grp  = lane >> 3;
    const int qd   = lane & 3;

    int len = lens[b];
    if (len < 1) len = 1;
    if (len > TT) len = TT;
    const int kcnt = (len + 15) >> 4;
    const float CSC = 0.36067376022224085f;   // 0.25 * log2(e)

    // ================= Phase 1: QKV GEMM =================
    if (w < 13) {
        const u32 a_base = sb + FU_X +
            (u32)((w * 16 + (grp & 1) * 8 + (lane & 7)) * 144 + (grp >> 1) * 16);
        const u32 b_base = sb + FU_W +
            (u32)(((grp >> 1) * 8 + (lane & 7)) * 144 + (grp & 1) * 16);
        const int rA = w * 16 + (lane >> 2);
        const int rB = rA + 8;

        #pragma unroll
        for (int nc = 0; nc < 4; nc++) {
            float acc[6][4];
            #pragma unroll
            for (int j = 0; j < 6; j++)
                #pragma unroll
                for (int q = 0; q < 4; q++) acc[j][q] = 0.f;

            #pragma unroll
            for (int ks = 0; ks < 4; ks++) {
                const u32 kb = (u32)(ks * 32);
                u32 A[4];
                ldmx4(A[0], A[1], A[2], A[3], a_base + kb);
                #pragma unroll
                for (int jp = 0; jp < 3; jp++) {
                    u32 Bh[4];
                    ldmx4(Bh[0], Bh[1], Bh[2], Bh[3],
                          b_base + (u32)(nc * 6912 + jp * 2304) + kb);
                    mma16816(acc[jp * 2],     A, Bh[0], Bh[1]);
                    mma16816(acc[jp * 2 + 1], A, Bh[2], Bh[3]);
                }
            }
            #pragma unroll
            for (int j = 0; j < 6; j++) {
                const int c = nc * 48 + 8 * j + 2 * qd;
                const float sc = (c < UU) ? CSC : 1.0f;
                *(u32*)(sm + FU_QKV + rA * 400 + c * 2) =
                    bfx2(acc[j][0] * sc, acc[j][1] * sc);
                *(u32*)(sm + FU_QKV + rB * 400 + c * 2) =
                    bfx2(acc[j][2] * sc, acc[j][3] * sc);
            }
        }
    }
    __syncthreads();

    // ================= Phase 2: attention =================
    {
        const u32 arow = (u32)(((grp & 1) * 8 + (lane & 7)) * 400 + (grp >> 1) * 16);
        const u32 krow = (u32)(((grp >> 1) * 8 + (lane & 7)) * 400 + (grp & 1) * 16);
        const u32 vrow = (u32)(((grp & 1) * 8 + (lane & 7)) * 400 + (grp >> 1) * 16);

        for (int t = w; t < 52; t += 16) {
            const int hh = t / 13;
            const int mm = t - hh * 13;
            const u32 hb = (u32)(hh * 32);

            u32 A[4];
            ldmx4(A[0], A[1], A[2], A[3],
                  sb + FU_QKV + (u32)(mm * 16) * 400 + hb + arow);
            const u32 ka = sb + FU_QKV + 128 + hb + krow;
            const u32 va = sb + FU_QKV + 256 + hb + vrow;

            float o0[4] = {0,0,0,0}, o1[4] = {0,0,0,0};
            ull lA = 0, lB = 0;

            for (int np = 0; np < kcnt; np++) {
                u32 KB[4], VB[4];
                ldmx4(KB[0], KB[1], KB[2], KB[3], ka + (u32)(np * 6400));
                ldmx4t(VB[0], VB[1], VB[2], VB[3], va + (u32)(np * 6400));

                const int c0 = np * 16 + 2 * qd;
                const ull m0 = pack2(c0 < len ? 1.f : 0.f, (c0 + 1) < len ? 1.f : 0.f);
                const ull m1 = pack2((c0 + 8) < len ? 1.f : 0.f, (c0 + 9) < len ? 1.f : 0.f);

                u32 aE[4];
                #pragma unroll
                for (int sub = 0; sub < 2; sub++) {
                    float s[4] = {0.f, 0.f, 0.f, 0.f};
                    mma16816(s, A, KB[sub * 2], KB[sub * 2 + 1]);
                    const ull m = sub ? m1 : m0;
                    const ull eA = fmul2(exp2p(pack2(s[0], s[1])), m);
                    const ull eB = fmul2(exp2p(pack2(s[2], s[3])), m);
                    lA = fadd2(lA, eA);
                    lB = fadd2(lB, eB);
                    aE[sub * 2]     = cvt_bf16x2p(eA);
                    aE[sub * 2 + 1] = cvt_bf16x2p(eB);
                }
                mma16816(o0, aE, VB[0], VB[1]);
                mma16816(o1, aE, VB[2], VB[3]);
            }

            // normalize + store O (bf16) into the retired X buffer
            float x, y;
            unpack2(lA, x, y); float la = x + y;
            la += __shfl_xor_sync(0xFFFFFFFFu, la, 1);
            la += __shfl_xor_sync(0xFFFFFFFFu, la, 2);
            unpack2(lB, x, y); float lb = x + y;
            lb += __shfl_xor_sync(0xFFFFFFFFu, lb, 1);
            lb += __shfl_xor_sync(0xFFFFFFFFu, lb, 2);
            const float iA = 1.f / la, iB = 1.f / lb;
            const int cb = hh * 16 + 2 * qd;
            const int rA = mm * 16 + (lane >> 2), rB = rA + 8;
            if (rA < TT) {
                *(u32*)(sm + FU_X + rA * 144 + cb * 2)      = bfx2(o0[0] * iA, o0[1] * iA);
                *(u32*)(sm + FU_X + rA * 144 + cb * 2 + 16) = bfx2(o1[0] * iA, o1[1] * iA);
            }
            if (rB < TT) {
                *(u32*)(sm + FU_X + rB * 144 + cb * 2)      = bfx2(o0[2] * iB, o0[3] * iB);
                *(u32*)(sm + FU_X + rB * 144 + cb * 2 + 16) = bfx2(o1[2] * iB, o1[3] * iB);
            }
        }
    }
    __syncthreads();

    // ================= Phase 3: projection + residual + LN =================
    if (w < 13) {
        const u32 a_base = sb + FU_X +
            (u32)((w * 16 + (grp & 1) * 8 + (lane & 7)) * 144 + (grp >> 1) * 16);
        const u32 b_base = sb + FU_WO +
            (u32)(((grp >> 1) * 8 + (lane & 7)) * 144 + (grp & 1) * 16);

        float acc[8][4];
        #pragma unroll
        for (int j = 0; j < 8; j++)
            #pragma unroll
            for (int q = 0; q < 4; q++) acc[j][q] = 0.f;

        #pragma unroll
        for (int ks = 0; ks < 4; ks++) {
            const u32 kb = (u32)(ks * 32);
            u32 Af[4];
            ldmx4(Af[0], Af[1], Af[2], Af[3], a_base + kb);
            #pragma unroll
            for (int jp = 0; jp < 4; jp++) {
                u32 Bh[4];
                ldmx4(Bh[0], Bh[1], Bh[2], Bh[3], b_base + (u32)(jp * 2304) + kb);
                mma16816(acc[jp * 2],     Af, Bh[0], Bh[1]);
                mma16816(acc[jp * 2 + 1], Af, Bh[2], Bh[3]);
            }
        }

        const int rAl = w * 16 + (lane >> 2);
        const int rBl = rAl + 8;
        const bool okB = rBl < TT;
        const size_t rowA = rowg0 + rAl;
        const size_t rowB = rowg0 + rBl;
        const int cq = 2 * qd;

        #pragma unroll
        for (int j = 0; j < 8; j++) {
            const int c = 8 * j + cq;
            float2 xa = *(const float2*)(X + rowA * UU + c);
            acc[j][0] += xa.x; acc[j][1] += xa.y;
            if (okB) {
                float2 xb = *(const float2*)(X + rowB * UU + c);
                acc[j][2] += xb.x; acc[j][3] += xb.y;
            }
        }

        float sA = 0.f, sB = 0.f;
        #pragma unroll
        for (int j = 0; j < 8; j++) {
            sA += acc[j][0] + acc[j][1];
            sB += acc[j][2] + acc[j][3];
        }
        sA += __shfl_xor_sync(0xFFFFFFFFu, sA, 1);
        sA += __shfl_xor_sync(0xFFFFFFFFu, sA, 2);
        sB += __shfl_xor_sync(0xFFFFFFFFu, sB, 1);
        sB += __shfl_xor_sync(0xFFFFFFFFu, sB, 2);
        const float mA = sA * (1.0f / 64.0f);
        const float mB = sB * (1.0f / 64.0f);

        float vA = 0.f, vB = 0.f;
        #pragma unroll
        for (int j = 0; j < 8; j++) {
            float d0 = acc[j][0] - mA, d1 = acc[j][1] - mA;
            float d2 = acc[j][2] - mB, d3 = acc[j][3] - mB;
            vA = fmaf(d0, d0, fmaf(d1, d1, vA));
            vB = fmaf(d2, d2, fmaf(d3, d3, vB));
        }
        vA += __shfl_xor_sync(0xFFFFFFFFu, vA, 1);
        vA += __shfl_xor_sync(0xFFFFFFFFu, vA, 2);
        vB += __shfl_xor_sync(0xFFFFFFFFu, vB, 1);
        vB += __shfl_xor_sync(0xFFFFFFFFu, vB, 2);
        const float iA = rsqrtf(vA * (1.0f / 64.0f) + 1e-9f);
        const float iB = rsqrtf(vB * (1.0f / 64.0f) + 1e-9f);

        #pragma unroll
        for (int j = 0; j < 8; j++) {
            const int c = 8 * j + cq;
            const float2 gg = *(const float2*)(gamma + c);
            const float2 bb = *(const float2*)(beta + c);
            float2 oa;
            oa.x = fmaf((acc[j][0] - mA) * iA, gg.x, bb.x);
            oa.y = fmaf((acc[j][1] - mA) * iA, gg.y, bb.y);
            *(float2*)(out + rowA * UU + c) = oa;
            if (okB) {
                float2 ob;
                ob.x = fmaf((acc[j][2] - mB) * iB, gg.x, bb.x);
                ob.y = fmaf((acc[j][3] - mB) * iB, gg.y, bb.y);
                *(float2*)(out + rowB * UU + c) = ob;
            }
        }
    }
}

// ---------------------------------------------------------------------------
extern "C" void kernel_launch(void* const* d_in, const int* in_sizes, int n_in,
                              void* d_out, int out_size)
{
    const float* input_info = (const float*)d_in[0];
    const int*   keys_len   = (const int*)d_in[1];
    const float* W          = (const float*)d_in[2];
    const float* W_output   = (const float*)d_in[3];
    const float* gamma      = (const float*)d_in[4];
    const float* beta       = (const float*)d_in[5];
    float* out = (float*)d_out;

    cudaFuncSetAttribute(fused_mha, cudaFuncAttributeMaxDynamicSharedMemorySize, FU_SMEM);

    prep_weights<<<64, 256>>>(W, W_output);
    fused_mha<<<BB, 512, FU_SMEM>>>(input_info, keys_len, gamma, beta, out);
}